// round 1
// baseline (speedup 1.0000x reference)
#include <cuda_runtime.h>
#include <cstdint>
#include <cstddef>

#define T_STEPS 4096
#define IN_DIM  128
#define HIDDEN  2048
#define LEAK    0.9f
#define NCTA    128
#define TPB     512
#define ROWS_PER_CTA 16   // HIDDEN / NCTA

// ---------------- device scratch (static: no allocations allowed) ----------------
__device__ float g_inp[(size_t)T_STEPS * HIDDEN];   // precomputed input projection [T,H]
__device__ float g_actbuf[2][HIDDEN];               // double-buffered activation vector
__device__ unsigned long long g_count;              // barrier ticket (monotonic across replays)
__device__ unsigned long long g_sense;              // barrier generation (monotonic)

// ---------------- packed fp32x2 helpers (Blackwell FFMA2) ----------------
__device__ __forceinline__ unsigned long long pack2(float lo, float hi) {
    unsigned long long u;
    asm("mov.b64 %0, {%1, %2};" : "=l"(u) : "f"(lo), "f"(hi));
    return u;
}
__device__ __forceinline__ void unpack2(unsigned long long u, float& lo, float& hi) {
    asm("mov.b64 {%0, %1}, %2;" : "=f"(lo), "=f"(hi) : "l"(u));
}
__device__ __forceinline__ unsigned long long ffma2(unsigned long long a,
                                                    unsigned long long b,
                                                    unsigned long long c) {
    unsigned long long d;
    asm("fma.rn.f32x2 %0, %1, %2, %3;" : "=l"(d) : "l"(a), "l"(b), "l"(c));
    return d;
}

// ---------------- init: zero act buffers each launch (replay-safe) ----------------
__global__ void init_kernel() {
    int tid = blockIdx.x * blockDim.x + threadIdx.x;
    if (tid < HIDDEN) {
        g_actbuf[0][tid] = 0.0f;
        g_actbuf[1][tid] = 0.0f;
    }
}

// ---------------- phase A: inp_proj[t][h] = input[t,:] . w_ih[h,:] + b_ih[h] ----------------
// grid: T/16 blocks of 256 threads; each thread handles 8 h's for 16 t's.
__global__ void inp_proj_kernel(const float* __restrict__ input,
                                const float* __restrict__ w_ih,
                                const float* __restrict__ b_ih) {
    __shared__ float s_in[16 * IN_DIM];
    const int tblk = blockIdx.x;
    const int tid  = threadIdx.x;

    for (int i = tid; i < 16 * IN_DIM; i += 256)
        s_in[i] = input[(size_t)tblk * 16 * IN_DIM + i];
    __syncthreads();

    const float4* s_in4 = reinterpret_cast<const float4*>(s_in);

    for (int j = 0; j < 8; j++) {
        const int h = tid + 256 * j;
        float acc[16];
        const float b = b_ih[h];
#pragma unroll
        for (int t = 0; t < 16; t++) acc[t] = b;

        const float4* wrow = reinterpret_cast<const float4*>(w_ih + (size_t)h * IN_DIM);
#pragma unroll 4
        for (int kc = 0; kc < IN_DIM / 4; kc++) {
            const float4 w4 = wrow[kc];
#pragma unroll
            for (int t = 0; t < 16; t++) {
                const float4 iv = s_in4[t * (IN_DIM / 4) + kc];  // warp-broadcast
                acc[t] += w4.x * iv.x + w4.y * iv.y + w4.z * iv.z + w4.w * iv.w;
            }
        }
#pragma unroll
        for (int t = 0; t < 16; t++)
            g_inp[(size_t)(tblk * 16 + t) * HIDDEN + h] = acc[t];
    }
}

// ---------------- phase B: persistent recurrence kernel ----------------
// 128 CTAs (one per SM, all resident) x 512 threads.
// CTA b owns rows [16b, 16b+16). Thread (rg = tid>>7, c = tid&127) owns
// rows {16b + 4rg + r : r<4} x cols {c + 128k : k<16}: 64 weights in registers.
__global__ void __launch_bounds__(TPB, 1)
reservoir_kernel(const float* __restrict__ w_hh,
                 float* __restrict__ out_act,
                 float* __restrict__ out_hid) {
    __shared__ float s_act[HIDDEN];
    __shared__ float s_part[ROWS_PER_CTA][4];
    __shared__ float s_hid[ROWS_PER_CTA];

    const int cta = blockIdx.x;
    const int tid = threadIdx.x;
    const int rg  = tid >> 7;        // row group 0..3 (4 rows each)
    const int c   = tid & 127;       // column thread 0..127
    const int wgrp = c >> 5;         // warp within row group 0..3

    // Load this thread's 64 weights into registers, packed for f32x2.
    // Pair k pairs cols (c + 256k, c + 256k + 128).
    unsigned long long W[4][8];
#pragma unroll
    for (int r = 0; r < 4; r++) {
        const int row = cta * ROWS_PER_CTA + rg * 4 + r;
        const float* wr = w_hh + (size_t)row * HIDDEN;
#pragma unroll
        for (int k = 0; k < 8; k++) {
            const float lo = wr[c + 256 * k];
            const float hi = wr[c + 256 * k + 128];
            W[r][k] = pack2(lo, hi);
        }
    }
    if (tid < ROWS_PER_CTA) s_hid[tid] = 0.0f;
    const int myrow = cta * ROWS_PER_CTA + tid;   // meaningful for tid < 16
    __syncthreads();

    for (int t = 0; t < T_STEPS; t++) {
        // ---- stage act_{t-1} from global (written by all CTAs last step) ----
        const float4 av4 = reinterpret_cast<const float4*>(g_actbuf[t & 1])[tid];
        reinterpret_cast<float4*>(s_act)[tid] = av4;

        float u = 0.0f;
        if (tid < ROWS_PER_CTA) u = g_inp[(size_t)t * HIDDEN + myrow];
        __syncthreads();

        // ---- partial dot products: 4 rows x 16 cols per thread, packed fp32x2 ----
        unsigned long long S0 = 0ull, S1 = 0ull, S2 = 0ull, S3 = 0ull;
#pragma unroll
        for (int k = 0; k < 8; k++) {
            const float a0 = s_act[c + 256 * k];
            const float a1 = s_act[c + 256 * k + 128];
            const unsigned long long A = pack2(a0, a1);
            S0 = ffma2(W[0][k], A, S0);
            S1 = ffma2(W[1][k], A, S1);
            S2 = ffma2(W[2][k], A, S2);
            S3 = ffma2(W[3][k], A, S3);
        }
        float v[4];
        {
            float lo, hi;
            unpack2(S0, lo, hi); v[0] = lo + hi;
            unpack2(S1, lo, hi); v[1] = lo + hi;
            unpack2(S2, lo, hi); v[2] = lo + hi;
            unpack2(S3, lo, hi); v[3] = lo + hi;
        }
        // ---- warp reduce each row partial ----
#pragma unroll
        for (int r = 0; r < 4; r++) {
#pragma unroll
            for (int off = 16; off; off >>= 1)
                v[r] += __shfl_xor_sync(0xffffffffu, v[r], off);
        }
        if ((c & 31) == 0) {
#pragma unroll
            for (int r = 0; r < 4; r++) s_part[rg * 4 + r][wgrp] = v[r];
        }
        __syncthreads();

        // ---- finalize: leak + tanh + stores (16 threads) ----
        if (tid < ROWS_PER_CTA) {
            const float dot = s_part[tid][0] + s_part[tid][1] + s_part[tid][2] + s_part[tid][3];
            const float nh = (1.0f - LEAK) * s_hid[tid] + LEAK * (u + dot);
            const float na = tanhf(nh);
            s_hid[tid] = nh;
            out_act[(size_t)t * HIDDEN + myrow] = na;
            out_hid[(size_t)t * HIDDEN + myrow] = nh;
            g_actbuf[(t + 1) & 1][myrow] = na;
        }
        __syncthreads();

        // ---- grid-wide barrier: ticket + generation (monotonic, replay-safe) ----
        if (tid == 0) {
            __threadfence();
            const unsigned long long ticket = atomicAdd(&g_count, 1ull);
            const unsigned long long target = ticket / NCTA + 1ull;
            if ((ticket % NCTA) == (NCTA - 1)) {
                __threadfence();
                *((volatile unsigned long long*)&g_sense) = target;
            } else {
                while (*((volatile unsigned long long*)&g_sense) < target) { }
            }
            __threadfence();
        }
        __syncthreads();
    }
}

// ---------------- launch ----------------
extern "C" void kernel_launch(void* const* d_in, const int* in_sizes, int n_in,
                              void* d_out, int out_size) {
    const float* input = (const float*)d_in[0];   // [T, IN_DIM]
    const float* w_ih  = (const float*)d_in[1];   // [H, IN_DIM]
    const float* b_ih  = (const float*)d_in[2];   // [H]
    const float* w_hh  = (const float*)d_in[3];   // [H, H]

    float* out_act = (float*)d_out;                          // [T, H]
    float* out_hid = (float*)d_out + (size_t)T_STEPS * HIDDEN; // [T, H]

    init_kernel<<<(HIDDEN + 255) / 256, 256>>>();
    inp_proj_kernel<<<T_STEPS / 16, 256>>>(input, w_ih, b_ih);
    reservoir_kernel<<<NCTA, TPB>>>(w_hh, out_act, out_hid);
}

// round 2
// speedup vs baseline: 1.4532x; 1.4532x over previous
#include <cuda_runtime.h>
#include <cstdint>
#include <cstddef>

#define T_STEPS 4096
#define IN_DIM  128
#define HIDDEN  2048
#define LEAK    0.9f
#define NCTA    128
#define TPB     512
#define ROWS_PER_CTA 16   // HIDDEN / NCTA

// ---------------- device scratch (static: no allocations allowed) ----------------
__device__ float g_inp[(size_t)T_STEPS * HIDDEN];   // precomputed input projection [T,H]
__device__ float g_actbuf[2][HIDDEN];               // double-buffered activation vector
__device__ unsigned long long g_count;              // barrier counter (monotonic across replays)

// ---------------- packed fp32x2 helpers (Blackwell FFMA2) ----------------
__device__ __forceinline__ unsigned long long pack2(float lo, float hi) {
    unsigned long long u;
    asm("mov.b64 %0, {%1, %2};" : "=l"(u) : "f"(lo), "f"(hi));
    return u;
}
__device__ __forceinline__ void unpack2(unsigned long long u, float& lo, float& hi) {
    asm("mov.b64 {%0, %1}, %2;" : "=f"(lo), "=f"(hi) : "l"(u));
}
__device__ __forceinline__ unsigned long long ffma2(unsigned long long a,
                                                    unsigned long long b,
                                                    unsigned long long c) {
    unsigned long long d;
    asm("fma.rn.f32x2 %0, %1, %2, %3;" : "=l"(d) : "l"(a), "l"(b), "l"(c));
    return d;
}

// ---------------- release/acquire barrier primitives (no MEMBAR) ----------------
__device__ __forceinline__ unsigned long long arrive_acqrel(unsigned long long* p) {
    unsigned long long old;
    asm volatile("atom.add.acq_rel.gpu.global.u64 %0, [%1], 1;"
                 : "=l"(old) : "l"(p) : "memory");
    return old;
}
__device__ __forceinline__ unsigned long long ld_acquire(unsigned long long* p) {
    unsigned long long v;
    asm volatile("ld.acquire.gpu.global.u64 %0, [%1];"
                 : "=l"(v) : "l"(p) : "memory");
    return v;
}

// ---------------- phase A: inp_proj[t][h] = input[t,:] . w_ih[h,:] + b_ih[h] ----------------
__global__ void inp_proj_kernel(const float* __restrict__ input,
                                const float* __restrict__ w_ih,
                                const float* __restrict__ b_ih) {
    __shared__ float s_in[16 * IN_DIM];
    const int tblk = blockIdx.x;
    const int tid  = threadIdx.x;

    for (int i = tid; i < 16 * IN_DIM; i += 256)
        s_in[i] = input[(size_t)tblk * 16 * IN_DIM + i];
    __syncthreads();

    const float4* s_in4 = reinterpret_cast<const float4*>(s_in);

    for (int j = 0; j < 8; j++) {
        const int h = tid + 256 * j;
        float acc[16];
        const float b = b_ih[h];
#pragma unroll
        for (int t = 0; t < 16; t++) acc[t] = b;

        const float4* wrow = reinterpret_cast<const float4*>(w_ih + (size_t)h * IN_DIM);
#pragma unroll 4
        for (int kc = 0; kc < IN_DIM / 4; kc++) {
            const float4 w4 = wrow[kc];
#pragma unroll
            for (int t = 0; t < 16; t++) {
                const float4 iv = s_in4[t * (IN_DIM / 4) + kc];  // warp-broadcast
                acc[t] += w4.x * iv.x + w4.y * iv.y + w4.z * iv.z + w4.w * iv.w;
            }
        }
#pragma unroll
        for (int t = 0; t < 16; t++)
            g_inp[(size_t)(tblk * 16 + t) * HIDDEN + h] = acc[t];
    }
}

// ---------------- phase B: persistent recurrence kernel ----------------
// 128 CTAs x 512 threads. CTA b owns rows [16b, 16b+16).
// Thread (rg = tid>>7, c = tid&127) owns rows {16b+4rg+r : r<4} x
// cols {c+128k : k<16} = 64 weights in registers (32 packed f32x2).
__global__ void __launch_bounds__(TPB, 1)
reservoir_kernel(const float* __restrict__ w_hh,
                 float* __restrict__ out_act,
                 float* __restrict__ out_hid) {
    __shared__ float s_act[HIDDEN];
    __shared__ float s_part[ROWS_PER_CTA][4];
    __shared__ float s_hid[ROWS_PER_CTA];

    const int cta = blockIdx.x;
    const int tid = threadIdx.x;
    const int rg  = tid >> 7;        // row group 0..3 (4 rows each)
    const int c   = tid & 127;       // column thread 0..127
    const int wgrp = c >> 5;         // warp within row group 0..3

    // Load this thread's 64 weights into registers, packed for f32x2.
    unsigned long long W[4][8];
#pragma unroll
    for (int r = 0; r < 4; r++) {
        const int row = cta * ROWS_PER_CTA + rg * 4 + r;
        const float* wr = w_hh + (size_t)row * HIDDEN;
#pragma unroll
        for (int k = 0; k < 8; k++) {
            const float lo = wr[c + 256 * k];
            const float hi = wr[c + 256 * k + 128];
            W[r][k] = pack2(lo, hi);
        }
    }
    if (tid < ROWS_PER_CTA) s_hid[tid] = 0.0f;
    const int myrow = cta * ROWS_PER_CTA + tid;   // meaningful for tid < 16
    __syncthreads();

    for (int t = 0; t < T_STEPS; t++) {
        // ---- stage act_{t-1} from global (t=0: act is all-zero, skip) ----
        if (t > 0) {
            const float4 av4 = reinterpret_cast<const float4*>(g_actbuf[t & 1])[tid];
            reinterpret_cast<float4*>(s_act)[tid] = av4;
        }

        float u = 0.0f;
        if (tid < ROWS_PER_CTA) u = g_inp[(size_t)t * HIDDEN + myrow];
        __syncthreads();

        if (t > 0) {
            // ---- partial dot products: 4 rows x 16 cols per thread ----
            unsigned long long S0 = 0ull, S1 = 0ull, S2 = 0ull, S3 = 0ull;
#pragma unroll
            for (int k = 0; k < 8; k++) {
                const float a0 = s_act[c + 256 * k];
                const float a1 = s_act[c + 256 * k + 128];
                const unsigned long long A = pack2(a0, a1);
                S0 = ffma2(W[0][k], A, S0);
                S1 = ffma2(W[1][k], A, S1);
                S2 = ffma2(W[2][k], A, S2);
                S3 = ffma2(W[3][k], A, S3);
            }
            float v[4];
            {
                float lo, hi;
                unpack2(S0, lo, hi); v[0] = lo + hi;
                unpack2(S1, lo, hi); v[1] = lo + hi;
                unpack2(S2, lo, hi); v[2] = lo + hi;
                unpack2(S3, lo, hi); v[3] = lo + hi;
            }
#pragma unroll
            for (int r = 0; r < 4; r++) {
#pragma unroll
                for (int off = 16; off; off >>= 1)
                    v[r] += __shfl_xor_sync(0xffffffffu, v[r], off);
            }
            if ((c & 31) == 0) {
#pragma unroll
                for (int r = 0; r < 4; r++) s_part[rg * 4 + r][wgrp] = v[r];
            }
        } else {
            // t == 0: act is zero -> all partials zero
            if ((c & 31) == 0) {
#pragma unroll
                for (int r = 0; r < 4; r++) s_part[rg * 4 + r][wgrp] = 0.0f;
            }
        }
        __syncthreads();

        // ---- finalize: leak + tanh + stores (16 threads) ----
        if (tid < ROWS_PER_CTA) {
            const float dot = s_part[tid][0] + s_part[tid][1] + s_part[tid][2] + s_part[tid][3];
            const float nh = (1.0f - LEAK) * s_hid[tid] + LEAK * (u + dot);
            const float na = tanhf(nh);
            s_hid[tid] = nh;
            out_act[(size_t)t * HIDDEN + myrow] = na;
            out_hid[(size_t)t * HIDDEN + myrow] = nh;
            g_actbuf[(t + 1) & 1][myrow] = na;
        }
        __syncthreads();

        // ---- grid barrier: single counter, release/acquire, no MEMBAR ----
        // Skip after the last step: nobody reads act_{T}; counter stays a
        // multiple of NCTA per phase, so graph replays remain consistent.
        if (t < T_STEPS - 1) {
            if (tid == 0) {
                const unsigned long long ticket = arrive_acqrel(&g_count);
                const unsigned long long target = (ticket / NCTA + 1ull) * NCTA;
                if (ticket + 1ull != target) {
                    while (ld_acquire(&g_count) < target) { }
                }
            }
            __syncthreads();
        }
    }
}

// ---------------- launch ----------------
extern "C" void kernel_launch(void* const* d_in, const int* in_sizes, int n_in,
                              void* d_out, int out_size) {
    const float* input = (const float*)d_in[0];   // [T, IN_DIM]
    const float* w_ih  = (const float*)d_in[1];   // [H, IN_DIM]
    const float* b_ih  = (const float*)d_in[2];   // [H]
    const float* w_hh  = (const float*)d_in[3];   // [H, H]

    float* out_act = (float*)d_out;                            // [T, H]
    float* out_hid = (float*)d_out + (size_t)T_STEPS * HIDDEN; // [T, H]

    inp_proj_kernel<<<T_STEPS / 16, 256>>>(input, w_ih, b_ih);
    reservoir_kernel<<<NCTA, TPB>>>(w_hh, out_act, out_hid);
}

// round 3
// speedup vs baseline: 1.4779x; 1.0170x over previous
#include <cuda_runtime.h>
#include <cstdint>
#include <cstddef>

#define T_STEPS 4096
#define IN_DIM  128
#define HIDDEN  2048
#define LEAK    0.9f
#define NCTA    128
#define TPB     512
#define ROWS_PER_CTA 16   // HIDDEN / NCTA

// ---------------- device scratch (static: no allocations allowed) ----------------
__device__ float g_inp[(size_t)T_STEPS * HIDDEN];   // precomputed input projection [T,H]
__device__ float g_actbuf[2][HIDDEN];               // double-buffered activation vector
__device__ unsigned long long g_count;              // barrier counter (monotonic across replays)

// ---------------- packed fp32x2 helpers ----------------
__device__ __forceinline__ unsigned long long pack2(float lo, float hi) {
    unsigned long long u;
    asm("mov.b64 %0, {%1, %2};" : "=l"(u) : "f"(lo), "f"(hi));
    return u;
}
__device__ __forceinline__ void unpack2(unsigned long long u, float& lo, float& hi) {
    asm("mov.b64 {%0, %1}, %2;" : "=f"(lo), "=f"(hi) : "l"(u));
}
__device__ __forceinline__ unsigned long long ffma2(unsigned long long a,
                                                    unsigned long long b,
                                                    unsigned long long c) {
    unsigned long long d;
    asm("fma.rn.f32x2 %0, %1, %2, %3;" : "=l"(d) : "l"(a), "l"(b), "l"(c));
    return d;
}

// ---------------- release/acquire barrier primitives (no MEMBAR) ----------------
__device__ __forceinline__ unsigned long long arrive_acqrel(unsigned long long* p) {
    unsigned long long old;
    asm volatile("atom.add.acq_rel.gpu.global.u64 %0, [%1], 1;"
                 : "=l"(old) : "l"(p) : "memory");
    return old;
}
__device__ __forceinline__ unsigned long long ld_acquire(unsigned long long* p) {
    unsigned long long v;
    asm volatile("ld.acquire.gpu.global.u64 %0, [%1];"
                 : "=l"(v) : "l"(p) : "memory");
    return v;
}

// ---------------- phase A: inp_proj[t][h] = input[t,:] . w_ih[h,:] + b_ih[h] ----------------
__global__ void inp_proj_kernel(const float* __restrict__ input,
                                const float* __restrict__ w_ih,
                                const float* __restrict__ b_ih) {
    __shared__ float s_in[16 * IN_DIM];
    const int tblk = blockIdx.x;
    const int tid  = threadIdx.x;

    for (int i = tid; i < 16 * IN_DIM; i += 256)
        s_in[i] = input[(size_t)tblk * 16 * IN_DIM + i];
    __syncthreads();

    const float4* s_in4 = reinterpret_cast<const float4*>(s_in);

    for (int j = 0; j < 8; j++) {
        const int h = tid + 256 * j;
        float acc[16];
        const float b = b_ih[h];
#pragma unroll
        for (int t = 0; t < 16; t++) acc[t] = b;

        const float4* wrow = reinterpret_cast<const float4*>(w_ih + (size_t)h * IN_DIM);
#pragma unroll 4
        for (int kc = 0; kc < IN_DIM / 4; kc++) {
            const float4 w4 = wrow[kc];
#pragma unroll
            for (int t = 0; t < 16; t++) {
                const float4 iv = s_in4[t * (IN_DIM / 4) + kc];  // warp-broadcast
                acc[t] += w4.x * iv.x + w4.y * iv.y + w4.z * iv.z + w4.w * iv.w;
            }
        }
#pragma unroll
        for (int t = 0; t < 16; t++)
            g_inp[(size_t)(tblk * 16 + t) * HIDDEN + h] = acc[t];
    }
}

// ---------------- phase B: persistent recurrence kernel ----------------
// 128 CTAs x 512 threads. CTA b owns rows [16b, 16b+16).
// Thread tid owns ALL 16 rows x cols [4*tid, 4*tid+4): 64 weights =
// 32 packed f32x2 registers. Act float4 goes LDG -> regs -> FFMA2 directly
// (no smem staging). Reduction: value-splitting warp butterfly (16 shfl),
// then one tiny cross-warp smem pass.
__global__ void __launch_bounds__(TPB, 1)
reservoir_kernel(const float* __restrict__ w_hh,
                 float* __restrict__ out_act,
                 float* __restrict__ out_hid) {
    __shared__ float s_part[ROWS_PER_CTA][17];   // [row][warp], padded

    const int tid  = threadIdx.x;
    const int lane = tid & 31;
    const int w    = tid >> 5;                   // warp id 0..15
    const int base_row = blockIdx.x * ROWS_PER_CTA;

    // Load weights: W[r] = cols [4*tid, 4*tid+4) of row base_row + r.
    unsigned long long W[ROWS_PER_CTA][2];
#pragma unroll
    for (int r = 0; r < ROWS_PER_CTA; r++) {
        const float4 wv = reinterpret_cast<const float4*>(
            w_hh + (size_t)(base_row + r) * HIDDEN)[tid];
        W[r][0] = pack2(wv.x, wv.y);
        W[r][1] = pack2(wv.z, wv.w);
    }

    const int myrow = base_row + tid;   // meaningful for tid < 16
    float hid = 0.0f;

    // ---- t = 0 peeled: act vector is zero -> dot = 0 ----
    if (tid < ROWS_PER_CTA) {
        const float u0 = g_inp[myrow];
        const float nh = LEAK * u0;
        const float na = tanhf(nh);
        hid = nh;
        out_act[myrow] = na;
        out_hid[myrow] = nh;
        g_actbuf[1][myrow] = na;
    }

    for (int t = 1; t < T_STEPS; t++) {
        // prefetch u_t (not gated by the barrier)
        float u = 0.0f;
        if (tid < ROWS_PER_CTA) u = g_inp[(size_t)t * HIDDEN + myrow];

        __syncthreads();   // order all warps' step t-1 stores before arrival
        if (tid == 0) {
            const unsigned long long ticket = arrive_acqrel(&g_count);
            const unsigned long long target = (ticket / NCTA + 1ull) * NCTA;
            if (ticket + 1ull != target) {
                while (ld_acquire(&g_count) < target) { }
            }
        }
        __syncthreads();   // release to all warps

        // act slice straight into registers
        const float4 a = reinterpret_cast<const float4*>(g_actbuf[t & 1])[tid];
        const unsigned long long A0 = pack2(a.x, a.y);
        const unsigned long long A1 = pack2(a.z, a.w);

        // 16 independent 2-deep FFMA2 chains
        float v[ROWS_PER_CTA];
#pragma unroll
        for (int r = 0; r < ROWS_PER_CTA; r++) {
            unsigned long long P = ffma2(W[r][0], A0, 0ull);
            P = ffma2(W[r][1], A1, P);
            float lo, hi; unpack2(P, lo, hi);
            v[r] = lo + hi;
        }

        // ---- value-splitting warp butterfly: 16 values -> 1 per lane ----
        {
            const bool up = (lane & 16) != 0;
#pragma unroll
            for (int i = 0; i < 8; i++) {
                const float send = up ? v[i] : v[i + 8];
                const float recv = __shfl_xor_sync(0xffffffffu, send, 16);
                v[i] = (up ? v[i + 8] : v[i]) + recv;
            }
        }
        {
            const bool up = (lane & 8) != 0;
#pragma unroll
            for (int i = 0; i < 4; i++) {
                const float send = up ? v[i] : v[i + 4];
                const float recv = __shfl_xor_sync(0xffffffffu, send, 8);
                v[i] = (up ? v[i + 4] : v[i]) + recv;
            }
        }
        {
            const bool up = (lane & 4) != 0;
#pragma unroll
            for (int i = 0; i < 2; i++) {
                const float send = up ? v[i] : v[i + 2];
                const float recv = __shfl_xor_sync(0xffffffffu, send, 4);
                v[i] = (up ? v[i + 2] : v[i]) + recv;
            }
        }
        {
            const bool up = (lane & 2) != 0;
            const float send = up ? v[0] : v[1];
            const float recv = __shfl_xor_sync(0xffffffffu, send, 2);
            v[0] = (up ? v[1] : v[0]) + recv;
        }
        v[0] += __shfl_xor_sync(0xffffffffu, v[0], 1);

        // lane holds row (lane>>1)&15; even lanes publish per-warp partial
        const int vrow = (lane >> 1) & 15;
        if ((lane & 1) == 0) s_part[vrow][w] = v[0];
        __syncthreads();

        // ---- finalize: 16 threads sum 16 warp partials, leak + tanh + stores ----
        if (tid < ROWS_PER_CTA) {
            float dot = 0.0f;
#pragma unroll
            for (int j = 0; j < 16; j++) dot += s_part[tid][j];
            const float nh = (1.0f - LEAK) * hid + LEAK * (u + dot);
            const float na = tanhf(nh);
            hid = nh;
            out_act[(size_t)t * HIDDEN + myrow] = na;
            out_hid[(size_t)t * HIDDEN + myrow] = nh;
            g_actbuf[(t + 1) & 1][myrow] = na;
        }
        // next iteration's top __syncthreads orders these stores before arrival
    }
}

// ---------------- launch ----------------
extern "C" void kernel_launch(void* const* d_in, const int* in_sizes, int n_in,
                              void* d_out, int out_size) {
    const float* input = (const float*)d_in[0];   // [T, IN_DIM]
    const float* w_ih  = (const float*)d_in[1];   // [H, IN_DIM]
    const float* b_ih  = (const float*)d_in[2];   // [H]
    const float* w_hh  = (const float*)d_in[3];   // [H, H]

    float* out_act = (float*)d_out;                            // [T, H]
    float* out_hid = (float*)d_out + (size_t)T_STEPS * HIDDEN; // [T, H]

    inp_proj_kernel<<<T_STEPS / 16, 256>>>(input, w_ih, b_ih);
    reservoir_kernel<<<NCTA, TPB>>>(w_hh, out_act, out_hid);
}